// round 3
// baseline (speedup 1.0000x reference)
#include <cuda_runtime.h>
#include <math.h>

#define NN 1024
#define FD 512
#define TT 128
#define HH 512
#define W32 (NN/32)
#define TCUT 6          // compute d_t for t=1..TCUT; ||d_7|| < 1e-27 * ||x||
#define NAPPS 21        // sum_{t=1..6} t applications of negL

// ---------------- scratch (no allocation allowed; __device__ globals) -------
__device__ float    g_xln[NN * FD];          // layer-normed x  (d_0)
__device__ float    g_dbuf[2][NN * FD];      // ping-pong diffusion state
__device__ unsigned g_bits[NN * W32];        // 1024x1024 adjacency bitmap (dedup)
__device__ int      g_deg[NN];               // distinct out-degree per row
__device__ int      g_rowptr[NN + 1];
__device__ int      g_cols[32768];           // CSR columns (dedup'd, <= E)
__device__ float    g_sab[TT];
__device__ float    g_somab[TT];

// ---------------- init: clear bitmap/deg, compute beta schedules ------------
__global__ void k_init() {
    int idx = blockIdx.x * blockDim.x + threadIdx.x;
    if (idx < NN * W32) g_bits[idx] = 0u;
    if (idx < NN) g_deg[idx] = 0;
    if (idx == 0) {
        double ab = 1.0;
        for (int t = 0; t < TT; t++) {
            double s = -6.0 + 12.0 * (double)t / (double)(TT - 1);
            double beta = 1.0 / (1.0 + exp(-s)) * (0.02 - 1e-4) + 1e-4;
            ab *= (1.0 - beta);
            g_sab[t]   = (float)sqrt(ab);
            g_somab[t] = (float)sqrt(1.0 - ab);
        }
    }
}

// ---------------- edges: dedup via bitmap, count distinct per row -----------
__global__ void k_edges(const int* __restrict__ src, const int* __restrict__ dst, int e) {
    int i = blockIdx.x * blockDim.x + threadIdx.x;
    if (i >= e) return;
    int s = src[i], d = dst[i];
    unsigned m = 1u << (d & 31);
    unsigned old = atomicOr(&g_bits[s * W32 + (d >> 5)], m);
    if (!(old & m)) atomicAdd(&g_deg[s], 1);
}

// ---------------- rowptr: inclusive scan of degrees (one 1024-thread block) -
__global__ void k_scan() {
    __shared__ int sh[NN];
    int i = threadIdx.x;
    sh[i] = g_deg[i];
    __syncthreads();
    for (int off = 1; off < NN; off <<= 1) {
        int v = (i >= off) ? sh[i - off] : 0;
        __syncthreads();
        sh[i] += v;
        __syncthreads();
    }
    g_rowptr[i + 1] = sh[i];
    if (i == 0) g_rowptr[0] = 0;
}

// ---------------- fill CSR columns from bitmap ------------------------------
__global__ void k_fill() {
    int i = blockIdx.x * blockDim.x + threadIdx.x;
    if (i >= NN) return;
    int c = g_rowptr[i];
    #pragma unroll 4
    for (int w = 0; w < W32; w++) {
        unsigned b = g_bits[i * W32 + w];
        while (b) {
            int bit = __ffs(b) - 1;
            g_cols[c++] = w * 32 + bit;
            b &= b - 1;
        }
    }
}

// ---------------- block-wide dual reduction (128 threads) -------------------
__device__ __forceinline__ void blk_red2(float& a, float& b) {
    __shared__ float sh[8];
    #pragma unroll
    for (int o = 16; o; o >>= 1) {
        a += __shfl_down_sync(0xffffffffu, a, o);
        b += __shfl_down_sync(0xffffffffu, b, o);
    }
    int w = threadIdx.x >> 5;
    if ((threadIdx.x & 31) == 0) { sh[w] = a; sh[4 + w] = b; }
    __syncthreads();
    a = sh[0] + sh[1] + sh[2] + sh[3];
    b = sh[4] + sh[5] + sh[6] + sh[7];
    __syncthreads();
}

__device__ __forceinline__ float sgnf(float v) {
    return (v > 0.0f) ? 1.0f : ((v < 0.0f) ? -1.0f : 0.0f);
}

// ---------------- fused: LN(x), LN(noise), nz, base output, time_embed ------
// out[row]      = somab[t]*nz  (+ sab[0]*xln if t==0)
// out_te[row]   = table[t[row]]
// g_xln[row]    = LN(x) row  (d_0 for the SpMM chain)
__global__ void __launch_bounds__(128) k_ln(
    const float* __restrict__ x, const float* __restrict__ noise,
    const float* __restrict__ table, const int* __restrict__ tn,
    float* __restrict__ out)
{
    int row = blockIdx.x, tid = threadIdx.x;
    const float4 xv = ((const float4*)(x + (size_t)row * FD))[tid];
    const float4 nv = ((const float4*)(noise + (size_t)row * FD))[tid];

    float sx = xv.x + xv.y + xv.z + xv.w;
    float sn = nv.x + nv.y + nv.z + nv.w;
    blk_red2(sx, sn);
    float mux = sx * (1.0f / FD), mun = sn * (1.0f / FD);

    float4 xc = {xv.x - mux, xv.y - mux, xv.z - mux, xv.w - mux};
    float4 nc = {nv.x - mun, nv.y - mun, nv.z - mun, nv.w - mun};

    float vx = xc.x * xc.x + xc.y * xc.y + xc.z * xc.z + xc.w * xc.w;
    float vn = nc.x * nc.x + nc.y * nc.y + nc.z * nc.z + nc.w * nc.w;
    blk_red2(vx, vn);

    float sxi = 1.0f / sqrtf(vx * (1.0f / FD) + 1e-5f);
    float sni = 1.4142135623730951f / sqrtf(vn * (1.0f / FD) + 1e-5f);

    float4 xl = {xc.x * sxi, xc.y * sxi, xc.z * sxi, xc.w * sxi};
    ((float4*)(g_xln + (size_t)row * FD))[tid] = xl;

    int tv = tn[row];
    float somab = g_somab[tv];
    float4 o;
    o.x = somab * sgnf(xl.x) * fabsf(nc.x * sni);
    o.y = somab * sgnf(xl.y) * fabsf(nc.y * sni);
    o.z = somab * sgnf(xl.z) * fabsf(nc.z * sni);
    o.w = somab * sgnf(xl.w) * fabsf(nc.w * sni);
    if (tv == 0) {
        float sab = g_sab[0];
        o.x += sab * xl.x; o.y += sab * xl.y; o.z += sab * xl.z; o.w += sab * xl.w;
    }
    ((float4*)(out + (size_t)row * FD))[tid] = o;

    // time embedding gather (H == FD == 512)
    const float4 te = ((const float4*)(table + (size_t)tv * HH))[tid];
    ((float4*)(out + (size_t)NN * FD + (size_t)row * HH))[tid] = te;
}

// ---------------- one application of negL to d; fused checkpoint gather -----
// d'[i] = (1/n) * sum_{j in adj(i)} d[j]  -  rowsum_i * d[i]
// if gather_t >= 0 and t[i]==gather_t: out[i] += sab[gather_t]*d'[i]
__global__ void __launch_bounds__(128) k_spmm(
    int srcb, int dstb, const int* __restrict__ tn,
    float* __restrict__ out, int gather_t)
{
    const float* __restrict__ dsrc = (srcb < 0) ? g_xln : g_dbuf[srcb];
    float* __restrict__ ddst = g_dbuf[dstb];
    int row = blockIdx.x, tid = threadIdx.x;
    int beg = g_rowptr[row], end = g_rowptr[row + 1];

    float ax = 0.f, ay = 0.f, az = 0.f, aw = 0.f;
    #pragma unroll 4
    for (int e = beg; e < end; e++) {
        int j = g_cols[e];
        float4 v = ((const float4*)(dsrc + (size_t)j * FD))[tid];
        ax += v.x; ay += v.y; az += v.z; aw += v.w;
    }
    float rs = (float)(end - beg) * (1.0f / NN);
    float4 own = ((const float4*)(dsrc + (size_t)row * FD))[tid];
    float4 r;
    r.x = ax * (1.0f / NN) - rs * own.x;
    r.y = ay * (1.0f / NN) - rs * own.y;
    r.z = az * (1.0f / NN) - rs * own.z;
    r.w = aw * (1.0f / NN) - rs * own.w;
    ((float4*)(ddst + (size_t)row * FD))[tid] = r;

    if (gather_t >= 0 && tn[row] == gather_t) {
        float sab = g_sab[gather_t];
        float4 o = ((float4*)(out + (size_t)row * FD))[tid];
        o.x += sab * r.x; o.y += sab * r.y; o.z += sab * r.z; o.w += sab * r.w;
        ((float4*)(out + (size_t)row * FD))[tid] = o;
    }
}

// ---------------- orchestration ---------------------------------------------
extern "C" void kernel_launch(void* const* d_in, const int* in_sizes, int n_in,
                              void* d_out, int out_size) {
    const float* x     = (const float*)d_in[0];
    const float* noise = (const float*)d_in[1];
    const float* table = (const float*)d_in[2];
    const int*   src   = (const int*)d_in[3];
    const int*   dst   = (const int*)d_in[4];
    const int*   tn    = (const int*)d_in[5];
    int E = in_sizes[3];
    float* out = (float*)d_out;

    k_init<<<64, 512>>>();                       // 32768 threads: clear + schedules
    k_edges<<<(E + 255) / 256, 256>>>(src, dst, E);
    k_scan<<<1, 1024>>>();
    k_fill<<<4, 256>>>();
    k_ln<<<NN, 128>>>(x, noise, table, tn, out);

    // triangular checkpoints: after k applications, state = negL^k x;
    // k = t(t+1)/2 is exactly d_t.
    const int tri[TCUT] = {1, 3, 6, 10, 15, 21};
    int srcb = -1, ti = 0;
    for (int k = 1; k <= NAPPS; k++) {
        int dstb = (k & 1) ? 0 : 1;
        int gt = -1;
        if (ti < TCUT && k == tri[ti]) { gt = ti + 1; ti++; }
        k_spmm<<<NN, 128>>>(srcb, dstb, tn, out, gt);
        srcb = dstb;
    }
}

// round 7
// speedup vs baseline: 1.1777x; 1.1777x over previous
#include <cuda_runtime.h>
#include <math.h>

#define NN 1024
#define FD 512
#define TT 128
#define HH 512
#define W32 (NN/32)
#define CG 4                 // columns per block in fused kernel
#define NBLK (FD/CG)         // 128 blocks
#define FTHREADS 512         // 16 warps
#define NAPPS 6              // negL applications: d_1(@1), d_2(@3), d_3(@6); d_4 ~ 1e-11

// ---------------- scratch (__device__ globals; no allocation) ---------------
__device__ float          g_xln[NN * FD];
__device__ unsigned       g_bits[NN * W32];
__device__ int            g_rowptr[NN + 1];
__device__ unsigned short g_cols16[32768];
__device__ float          g_sab[TT];
__device__ float          g_somab[TT];

// ---------------- init: clear bitmap, compute beta schedules ----------------
__global__ void k_init() {
    int idx = blockIdx.x * blockDim.x + threadIdx.x;
    if (idx < NN * W32) g_bits[idx] = 0u;
    if (idx == 0) {
        double ab = 1.0;
        for (int t = 0; t < TT; t++) {
            double s = -6.0 + 12.0 * (double)t / (double)(TT - 1);
            double beta = 1.0 / (1.0 + exp(-s)) * (0.02 - 1e-4) + 1e-4;
            ab *= (1.0 - beta);
            g_sab[t]   = (float)sqrt(ab);
            g_somab[t] = (float)sqrt(1.0 - ab);
        }
    }
}

// ---------------- edges: dedup via bitmap ----------------------------------
__global__ void k_edges(const int* __restrict__ src, const int* __restrict__ dst, int e) {
    int i = blockIdx.x * blockDim.x + threadIdx.x;
    if (i >= e) return;
    int s = src[i], d = dst[i];
    atomicOr(&g_bits[s * W32 + (d >> 5)], 1u << (d & 31));
}

// ---------------- rowptr: degree from popcount + block scan -----------------
__global__ void k_scan() {
    __shared__ int sh[NN];
    int i = threadIdx.x;
    int deg = 0;
    #pragma unroll
    for (int w = 0; w < W32; w++) deg += __popc(g_bits[i * W32 + w]);
    sh[i] = deg;
    __syncthreads();
    for (int off = 1; off < NN; off <<= 1) {
        int v = (i >= off) ? sh[i - off] : 0;
        __syncthreads();
        sh[i] += v;
        __syncthreads();
    }
    g_rowptr[i + 1] = sh[i];
    if (i == 0) g_rowptr[0] = 0;
}

// ---------------- fill CSR columns: warp per row, ballot compaction ---------
__global__ void __launch_bounds__(256) k_fill() {
    int warp = (blockIdx.x * blockDim.x + threadIdx.x) >> 5;   // 0..1023 = row
    int lane = threadIdx.x & 31;
    unsigned b = g_bits[warp * W32 + lane];
    int cnt = __popc(b);
    // exclusive prefix over lanes
    int pre = cnt;
    #pragma unroll
    for (int o = 1; o < 32; o <<= 1) {
        int v = __shfl_up_sync(0xffffffffu, pre, o);
        if (lane >= o) pre += v;
    }
    pre -= cnt;
    int base = g_rowptr[warp] + pre;
    while (b) {
        int bit = __ffs(b) - 1;
        g_cols16[base++] = (unsigned short)(lane * 32 + bit);
        b &= b - 1;
    }
}

// ---------------- block-wide dual reduction (128 threads) -------------------
__device__ __forceinline__ void blk_red2(float& a, float& b) {
    __shared__ float sh[8];
    #pragma unroll
    for (int o = 16; o; o >>= 1) {
        a += __shfl_down_sync(0xffffffffu, a, o);
        b += __shfl_down_sync(0xffffffffu, b, o);
    }
    int w = threadIdx.x >> 5;
    if ((threadIdx.x & 31) == 0) { sh[w] = a; sh[4 + w] = b; }
    __syncthreads();
    a = sh[0] + sh[1] + sh[2] + sh[3];
    b = sh[4] + sh[5] + sh[6] + sh[7];
    __syncthreads();
}

__device__ __forceinline__ float sgnf(float v) {
    return (v > 0.0f) ? 1.0f : ((v < 0.0f) ? -1.0f : 0.0f);
}

// ---------------- fused: LN(x), LN(noise), nz, base out, time_embed ---------
__global__ void __launch_bounds__(128) k_ln(
    const float* __restrict__ x, const float* __restrict__ noise,
    const float* __restrict__ table, const int* __restrict__ tn,
    float* __restrict__ out)
{
    int row = blockIdx.x, tid = threadIdx.x;
    const float4 xv = ((const float4*)(x + (size_t)row * FD))[tid];
    const float4 nv = ((const float4*)(noise + (size_t)row * FD))[tid];

    float sx = xv.x + xv.y + xv.z + xv.w;
    float sn = nv.x + nv.y + nv.z + nv.w;
    blk_red2(sx, sn);
    float mux = sx * (1.0f / FD), mun = sn * (1.0f / FD);

    float4 xc = {xv.x - mux, xv.y - mux, xv.z - mux, xv.w - mux};
    float4 nc = {nv.x - mun, nv.y - mun, nv.z - mun, nv.w - mun};

    float vx = xc.x * xc.x + xc.y * xc.y + xc.z * xc.z + xc.w * xc.w;
    float vn = nc.x * nc.x + nc.y * nc.y + nc.z * nc.z + nc.w * nc.w;
    blk_red2(vx, vn);

    float sxi = 1.0f / sqrtf(vx * (1.0f / FD) + 1e-5f);
    float sni = 1.4142135623730951f / sqrtf(vn * (1.0f / FD) + 1e-5f);

    float4 xl = {xc.x * sxi, xc.y * sxi, xc.z * sxi, xc.w * sxi};
    ((float4*)(g_xln + (size_t)row * FD))[tid] = xl;

    int tv = tn[row];
    float somab = g_somab[tv];
    float4 o;
    o.x = somab * sgnf(xl.x) * fabsf(nc.x * sni);
    o.y = somab * sgnf(xl.y) * fabsf(nc.y * sni);
    o.z = somab * sgnf(xl.z) * fabsf(nc.z * sni);
    o.w = somab * sgnf(xl.w) * fabsf(nc.w * sni);
    if (tv == 0) {
        float sab = g_sab[0];
        o.x += sab * xl.x; o.y += sab * xl.y; o.z += sab * xl.z; o.w += sab * xl.w;
    }
    ((float4*)(out + (size_t)row * FD))[tid] = o;

    const float4 te = ((const float4*)(table + (size_t)tv * HH))[tid];
    ((float4*)(out + (size_t)NN * FD + (size_t)row * HH))[tid] = te;
}

// ---------------- fused diffusion chain: 6 negL applications, 1 kernel ------
// Block b owns feature columns [b*CG, b*CG+CG). Entire 1024-node state slice
// lives in smem (ping-pong). Lane layout: 8 row-groups x 4 cols per warp;
// each lane serially accumulates its (row, col) over the row's neighbor list
// (no warp reduction). Checkpoints after apps 1/3/6 add sab[t]*d_t into out
// for rows with t[i]==t.
__global__ void __launch_bounds__(FTHREADS) k_fused(
    const int* __restrict__ tn, float* __restrict__ out)
{
    __shared__ float sA[NN * CG];
    __shared__ float sB[NN * CG];
    __shared__ int   srp[NN + 1];
    __shared__ int   stn[NN];

    const int tid  = threadIdx.x;
    const int col0 = blockIdx.x * CG;
    const int lane = tid & 31;
    const int wid  = tid >> 5;          // 0..15
    const int rg   = lane >> 2;         // 0..7 row-group
    const int c    = lane & 3;          // 0..3 col

    for (int i = tid; i <= NN; i += FTHREADS) srp[i] = g_rowptr[i];
    for (int i = tid; i < NN; i += FTHREADS) stn[i] = tn[i];
    for (int r = tid; r < NN; r += FTHREADS)
        *(float4*)&sA[r * CG] = *(const float4*)&g_xln[(size_t)r * FD + col0];
    __syncthreads();

    float* cur = sA;
    float* nxt = sB;
    const float inv_n = 1.0f / NN;

    #pragma unroll
    for (int k = 1; k <= NAPPS; k++) {
        int want = (k == 1) ? 1 : (k == 3) ? 2 : (k == 6) ? 3 : -1;
        #pragma unroll 1
        for (int pass = 0; pass < NN / 128; pass++) {      // 8 passes x 128 rows
            int r = pass * 128 + wid * 8 + rg;
            int beg = srp[r], end = srp[r + 1];
            float acc = 0.0f;
            for (int e = beg; e < end; e++) {
                int j = (int)g_cols16[e];
                acc += cur[j * CG + c];
            }
            float rs  = (float)(end - beg) * inv_n;
            float res = acc * inv_n - rs * cur[r * CG + c];
            nxt[r * CG + c] = res;
            if (want >= 0 && stn[r] == want) {
                out[(size_t)r * FD + col0 + c] += g_sab[want] * res;
            }
        }
        __syncthreads();
        float* tmp = cur; cur = nxt; nxt = tmp;
    }
}

// ---------------- orchestration ---------------------------------------------
extern "C" void kernel_launch(void* const* d_in, const int* in_sizes, int n_in,
                              void* d_out, int out_size) {
    const float* x     = (const float*)d_in[0];
    const float* noise = (const float*)d_in[1];
    const float* table = (const float*)d_in[2];
    const int*   src   = (const int*)d_in[3];
    const int*   dst   = (const int*)d_in[4];
    const int*   tn    = (const int*)d_in[5];
    int E = in_sizes[3];
    float* out = (float*)d_out;

    k_init<<<64, 512>>>();
    k_edges<<<(E + 255) / 256, 256>>>(src, dst, E);
    k_scan<<<1, 1024>>>();
    k_fill<<<NN / 8, 256>>>();                // warp per row: 1024 warps
    k_ln<<<NN, 128>>>(x, noise, table, tn, out);
    k_fused<<<NBLK, FTHREADS>>>(tn, out);
}

// round 8
// speedup vs baseline: 3.5905x; 3.0488x over previous
#include <cuda_runtime.h>
#include <math.h>

#define NN 1024
#define FD 512
#define TT 128
#define HH 512
#define W32 (NN/32)
#define CG 4                 // columns per block in fused kernel
#define NBLK (FD/CG)         // 128 blocks
#define FTHREADS 512         // 16 warps
#define NAPPS 6              // negL applications: d_1(@1), d_2(@3), d_3(@6); d_4 ~ 1e-11

// ---------------- scratch (__device__ globals; no allocation) ---------------
__device__ float          g_xln[NN * FD];
__device__ unsigned       g_bits[NN * W32];
__device__ int            g_rowptr[NN + 1];
__device__ unsigned short g_cols16[32768];
__device__ float          g_sab[TT];
__device__ float          g_somab[TT];

// ---------------- init: clear bitmap + PARALLEL beta schedule ---------------
// Schedule: betas from sigmoid ramp; alphas_bar = cumprod(1-beta).
// Computed in log space: ab_t = exp( sum_{i<=t} log1p(-beta_i) ) — a 128-wide
// parallel prefix instead of a single-thread serial DP cumprod chain.
__global__ void k_init() {
    int idx = blockIdx.x * blockDim.x + threadIdx.x;
    if (idx < NN * W32) g_bits[idx] = 0u;

    if (blockIdx.x == 0 && threadIdx.x < TT) {
        __shared__ double wsum[4];
        int t = threadIdx.x;                    // warps 0..3 fully active
        int lane = t & 31, w = t >> 5;
        double s = -6.0 + 12.0 * (double)t / (double)(TT - 1);
        double beta = 1.0 / (1.0 + exp(-s)) * (0.02 - 1e-4) + 1e-4;
        double lg = log1p(-beta);

        // inclusive prefix within warp (double shfl)
        double p = lg;
        #pragma unroll
        for (int o = 1; o < 32; o <<= 1) {
            double v = __shfl_up_sync(0xffffffffu, p, o);
            if (lane >= o) p += v;
        }
        if (lane == 31) wsum[w] = p;
        __syncthreads();
        double base = 0.0;
        #pragma unroll
        for (int ww = 0; ww < 4; ww++) if (ww < w) base += wsum[ww];

        double ab = exp(base + p);
        g_sab[t]   = (float)sqrt(ab);
        g_somab[t] = (float)sqrt(1.0 - ab);
    }
}

// ---------------- edges: dedup via bitmap ----------------------------------
__global__ void k_edges(const int* __restrict__ src, const int* __restrict__ dst, int e) {
    int i = blockIdx.x * blockDim.x + threadIdx.x;
    if (i >= e) return;
    int s = src[i], d = dst[i];
    atomicOr(&g_bits[s * W32 + (d >> 5)], 1u << (d & 31));
}

// ---------------- rowptr: degree from popcount + block scan -----------------
__global__ void k_scan() {
    __shared__ int sh[NN];
    int i = threadIdx.x;
    int deg = 0;
    #pragma unroll
    for (int w = 0; w < W32; w++) deg += __popc(g_bits[i * W32 + w]);
    sh[i] = deg;
    __syncthreads();
    for (int off = 1; off < NN; off <<= 1) {
        int v = (i >= off) ? sh[i - off] : 0;
        __syncthreads();
        sh[i] += v;
        __syncthreads();
    }
    g_rowptr[i + 1] = sh[i];
    if (i == 0) g_rowptr[0] = 0;
}

// ---------------- fill CSR columns: warp per row, ballot compaction ---------
__global__ void __launch_bounds__(256) k_fill() {
    int warp = (blockIdx.x * blockDim.x + threadIdx.x) >> 5;   // 0..1023 = row
    int lane = threadIdx.x & 31;
    unsigned b = g_bits[warp * W32 + lane];
    int cnt = __popc(b);
    int pre = cnt;
    #pragma unroll
    for (int o = 1; o < 32; o <<= 1) {
        int v = __shfl_up_sync(0xffffffffu, pre, o);
        if (lane >= o) pre += v;
    }
    pre -= cnt;
    int base = g_rowptr[warp] + pre;
    while (b) {
        int bit = __ffs(b) - 1;
        g_cols16[base++] = (unsigned short)(lane * 32 + bit);
        b &= b - 1;
    }
}

// ---------------- block-wide dual reduction (128 threads) -------------------
__device__ __forceinline__ void blk_red2(float& a, float& b) {
    __shared__ float sh[8];
    #pragma unroll
    for (int o = 16; o; o >>= 1) {
        a += __shfl_down_sync(0xffffffffu, a, o);
        b += __shfl_down_sync(0xffffffffu, b, o);
    }
    int w = threadIdx.x >> 5;
    if ((threadIdx.x & 31) == 0) { sh[w] = a; sh[4 + w] = b; }
    __syncthreads();
    a = sh[0] + sh[1] + sh[2] + sh[3];
    b = sh[4] + sh[5] + sh[6] + sh[7];
    __syncthreads();
}

__device__ __forceinline__ float sgnf(float v) {
    return (v > 0.0f) ? 1.0f : ((v < 0.0f) ? -1.0f : 0.0f);
}

// ---------------- fused: LN(x), LN(noise), nz, base out, time_embed ---------
__global__ void __launch_bounds__(128) k_ln(
    const float* __restrict__ x, const float* __restrict__ noise,
    const float* __restrict__ table, const int* __restrict__ tn,
    float* __restrict__ out)
{
    int row = blockIdx.x, tid = threadIdx.x;
    const float4 xv = ((const float4*)(x + (size_t)row * FD))[tid];
    const float4 nv = ((const float4*)(noise + (size_t)row * FD))[tid];

    float sx = xv.x + xv.y + xv.z + xv.w;
    float sn = nv.x + nv.y + nv.z + nv.w;
    blk_red2(sx, sn);
    float mux = sx * (1.0f / FD), mun = sn * (1.0f / FD);

    float4 xc = {xv.x - mux, xv.y - mux, xv.z - mux, xv.w - mux};
    float4 nc = {nv.x - mun, nv.y - mun, nv.z - mun, nv.w - mun};

    float vx = xc.x * xc.x + xc.y * xc.y + xc.z * xc.z + xc.w * xc.w;
    float vn = nc.x * nc.x + nc.y * nc.y + nc.z * nc.z + nc.w * nc.w;
    blk_red2(vx, vn);

    float sxi = 1.0f / sqrtf(vx * (1.0f / FD) + 1e-5f);
    float sni = 1.4142135623730951f / sqrtf(vn * (1.0f / FD) + 1e-5f);

    float4 xl = {xc.x * sxi, xc.y * sxi, xc.z * sxi, xc.w * sxi};
    ((float4*)(g_xln + (size_t)row * FD))[tid] = xl;

    int tv = tn[row];
    float somab = g_somab[tv];
    float4 o;
    o.x = somab * sgnf(xl.x) * fabsf(nc.x * sni);
    o.y = somab * sgnf(xl.y) * fabsf(nc.y * sni);
    o.z = somab * sgnf(xl.z) * fabsf(nc.z * sni);
    o.w = somab * sgnf(xl.w) * fabsf(nc.w * sni);
    if (tv == 0) {
        float sab = g_sab[0];
        o.x += sab * xl.x; o.y += sab * xl.y; o.z += sab * xl.z; o.w += sab * xl.w;
    }
    ((float4*)(out + (size_t)row * FD))[tid] = o;

    const float4 te = ((const float4*)(table + (size_t)tv * HH))[tid];
    ((float4*)(out + (size_t)NN * FD + (size_t)row * HH))[tid] = te;
}

// ---------------- fused diffusion chain: 6 negL applications, 1 kernel ------
__global__ void __launch_bounds__(FTHREADS) k_fused(
    const int* __restrict__ tn, float* __restrict__ out)
{
    __shared__ float sA[NN * CG];
    __shared__ float sB[NN * CG];
    __shared__ int   srp[NN + 1];
    __shared__ int   stn[NN];

    const int tid  = threadIdx.x;
    const int col0 = blockIdx.x * CG;
    const int lane = tid & 31;
    const int wid  = tid >> 5;          // 0..15
    const int rg   = lane >> 2;         // 0..7 row-group
    const int c    = lane & 3;          // 0..3 col

    for (int i = tid; i <= NN; i += FTHREADS) srp[i] = g_rowptr[i];
    for (int i = tid; i < NN; i += FTHREADS) stn[i] = tn[i];
    for (int r = tid; r < NN; r += FTHREADS)
        *(float4*)&sA[r * CG] = *(const float4*)&g_xln[(size_t)r * FD + col0];
    __syncthreads();

    float* cur = sA;
    float* nxt = sB;
    const float inv_n = 1.0f / NN;

    #pragma unroll
    for (int k = 1; k <= NAPPS; k++) {
        int want = (k == 1) ? 1 : (k == 3) ? 2 : (k == 6) ? 3 : -1;
        #pragma unroll 1
        for (int pass = 0; pass < NN / 128; pass++) {      // 8 passes x 128 rows
            int r = pass * 128 + wid * 8 + rg;
            int beg = srp[r], end = srp[r + 1];
            float acc = 0.0f;
            for (int e = beg; e < end; e++) {
                int j = (int)g_cols16[e];
                acc += cur[j * CG + c];
            }
            float rs  = (float)(end - beg) * inv_n;
            float res = acc * inv_n - rs * cur[r * CG + c];
            nxt[r * CG + c] = res;
            if (want >= 0 && stn[r] == want) {
                out[(size_t)r * FD + col0 + c] += g_sab[want] * res;
            }
        }
        __syncthreads();
        float* tmp = cur; cur = nxt; nxt = tmp;
    }
}

// ---------------- orchestration ---------------------------------------------
extern "C" void kernel_launch(void* const* d_in, const int* in_sizes, int n_in,
                              void* d_out, int out_size) {
    const float* x     = (const float*)d_in[0];
    const float* noise = (const float*)d_in[1];
    const float* table = (const float*)d_in[2];
    const int*   src   = (const int*)d_in[3];
    const int*   dst   = (const int*)d_in[4];
    const int*   tn    = (const int*)d_in[5];
    int E = in_sizes[3];
    float* out = (float*)d_out;

    k_init<<<64, 512>>>();
    k_edges<<<(E + 255) / 256, 256>>>(src, dst, E);
    k_scan<<<1, 1024>>>();
    k_fill<<<NN / 8, 256>>>();
    k_ln<<<NN, 128>>>(x, noise, table, tn, out);
    k_fused<<<NBLK, FTHREADS>>>(tn, out);
}

// round 9
// speedup vs baseline: 4.4364x; 1.2356x over previous
#include <cuda_runtime.h>
#include <math.h>

#define NN 1024
#define FD 512
#define TT 128
#define HH 512
#define W32 (NN/32)
#define GB  128            // persistent grid: 128 blocks <= 148 SMs (co-resident)
#define BT  512            // threads per block
#define MAXTGT NN

// ---------------- device globals (zero-init; restored clean at kernel end) --
__device__ unsigned       g_fwd[NN * W32];     // forward adjacency bitmap
__device__ unsigned       g_rev[NN * W32];     // reverse adjacency bitmap
__device__ int            g_rowptr[NN + 1];    // rev CSR rowptr (rebuilt each call)
__device__ unsigned short g_cols[32768];       // rev CSR cols
__device__ float          g_rowsum[NN];        // fwd distinct-degree / n
__device__ float          g_xln[NN * FD];      // LN(x)
__device__ float          g_sab[TT];
__device__ float          g_somab[TT];
__device__ int            g_trow[MAXTGT];
__device__ int            g_tt[MAXTGT];
__device__ int            g_tcount;            // cleared at end
__device__ float          g_wvec[(size_t)MAXTGT * NN];   // per-target propagated vectors
__device__ unsigned       g_bar_cnt;           // grid barrier state
__device__ unsigned       g_bar_gen;

// ---------------- grid barrier (all GB blocks resident by construction) -----
__device__ __forceinline__ void gbar() {
    __threadfence();
    __syncthreads();
    if (threadIdx.x == 0) {
        unsigned gen = *(volatile unsigned*)&g_bar_gen;
        if (atomicAdd(&g_bar_cnt, 1u) == GB - 1) {
            g_bar_cnt = 0;
            __threadfence();
            atomicExch(&g_bar_gen, gen + 1u);
        } else {
            while (*(volatile unsigned*)&g_bar_gen == gen) { }
        }
    }
    __syncthreads();
    __threadfence();
}

__device__ __forceinline__ float sgnf(float v) {
    return (v > 0.0f) ? 1.0f : ((v < 0.0f) ? -1.0f : 0.0f);
}

// ---------------- the whole problem in one persistent kernel ----------------
__global__ void __launch_bounds__(BT) k_all(
    const float* __restrict__ x, const float* __restrict__ noise,
    const float* __restrict__ table, const int* __restrict__ src,
    const int* __restrict__ dst, const int* __restrict__ tn,
    float* __restrict__ out, int E)
{
    __shared__ float  s_f[2048];      // chain ping-pong / contract w + staging
    __shared__ int    s_scan[2048];   // scan double-buffer
    __shared__ float  s_red[32];      // LN reductions
    __shared__ double s_wsum[4];      // schedule prefix

    const int bid = blockIdx.x, tid = threadIdx.x;
    const int g   = bid * BT + tid;

    // ===== Phase A: edges into bitmaps (pre-cleaned) + beta schedule ========
    for (int e = g; e < E; e += GB * BT) {
        int s = src[e], d = dst[e];
        atomicOr(&g_fwd[s * W32 + (d >> 5)], 1u << (d & 31));
        atomicOr(&g_rev[d * W32 + (s >> 5)], 1u << (s & 31));
    }
    if (bid == 0) {
        // parallel schedule: ab_t = exp(prefix of log1p(-beta))
        int lane = tid & 31, w = tid >> 5;
        double p = 0.0;
        if (tid < TT) {
            double s = -6.0 + 12.0 * (double)tid / (double)(TT - 1);
            double beta = 1.0 / (1.0 + exp(-s)) * (0.02 - 1e-4) + 1e-4;
            p = log1p(-beta);
            #pragma unroll
            for (int o = 1; o < 32; o <<= 1) {
                double v = __shfl_up_sync(0xffffffffu, p, o);
                if (lane >= o) p += v;
            }
            if (lane == 31) s_wsum[w] = p;
        }
        __syncthreads();
        if (tid < TT) {
            double base = 0.0;
            #pragma unroll
            for (int ww = 0; ww < 4; ww++) if (ww < w) base += s_wsum[ww];
            double ab = exp(base + p);
            g_sab[tid]   = (float)sqrt(ab);
            g_somab[tid] = (float)sqrt(1.0 - ab);
        }
    }
    gbar();

    // ===== Phase B: rev rowptr scan (block 0) | rowsum + target list ========
    if (bid == 0) {
        int* a = s_scan; int* b = s_scan + NN;
        for (int i = tid; i < NN; i += BT) {
            int d = 0;
            #pragma unroll
            for (int ww = 0; ww < W32; ww++) d += __popc(g_rev[i * W32 + ww]);
            a[i] = d;
        }
        __syncthreads();
        for (int off = 1; off < NN; off <<= 1) {
            for (int i = tid; i < NN; i += BT)
                b[i] = a[i] + ((i >= off) ? a[i - off] : 0);
            __syncthreads();
            int* t_ = a; a = b; b = t_;
        }
        for (int i = tid; i < NN; i += BT) g_rowptr[i + 1] = a[i];
        if (tid == 0) g_rowptr[0] = 0;
    } else {
        int i = (bid - 1) * BT + tid;
        if (i < NN) {
            int d = 0;
            #pragma unroll
            for (int ww = 0; ww < W32; ww++) d += __popc(g_fwd[i * W32 + ww]);
            g_rowsum[i] = (float)d * (1.0f / NN);
            int t = tn[i];
            if (t >= 1 && t <= 3) {
                int slot = atomicAdd(&g_tcount, 1);
                g_trow[slot] = i; g_tt[slot] = t;
            }
        }
    }
    gbar();
    const int ntgt = g_tcount;     // stable from here until end-of-kernel reset

    // ===== Phase C: fill rev CSR (warp/row) + LN/noise/base-out/time-emb ====
    {
        int gw = bid * (BT / 32) + (tid >> 5);
        int lane = tid & 31;
        if (gw < NN) {
            unsigned b = g_rev[gw * W32 + lane];
            int cnt = __popc(b);
            int pre = cnt;
            #pragma unroll
            for (int o = 1; o < 32; o <<= 1) {
                int v = __shfl_up_sync(0xffffffffu, pre, o);
                if (lane >= o) pre += v;
            }
            pre -= cnt;
            int base = g_rowptr[gw] + pre;
            while (b) {
                int bit = __ffs(b) - 1;
                g_cols[base++] = (unsigned short)(lane * 32 + bit);
                b &= b - 1;
            }
        }
    }
    __syncthreads();
    {
        // 4 groups of 128 threads; 2 iterations -> 8 rows per block
        int grp = tid >> 7, gt = tid & 127;
        int glane = gt & 31, gwp = gt >> 5;
        #pragma unroll
        for (int it = 0; it < 2; it++) {
            int row = bid * 8 + it * 4 + grp;
            const float4 xv = ((const float4*)(x + (size_t)row * FD))[gt];
            const float4 nv = ((const float4*)(noise + (size_t)row * FD))[gt];

            float sx = xv.x + xv.y + xv.z + xv.w;
            float sn = nv.x + nv.y + nv.z + nv.w;
            #pragma unroll
            for (int o = 16; o; o >>= 1) {
                sx += __shfl_down_sync(0xffffffffu, sx, o);
                sn += __shfl_down_sync(0xffffffffu, sn, o);
            }
            if (glane == 0) { s_red[grp * 4 + gwp] = sx; s_red[16 + grp * 4 + gwp] = sn; }
            __syncthreads();
            sx = s_red[grp*4+0] + s_red[grp*4+1] + s_red[grp*4+2] + s_red[grp*4+3];
            sn = s_red[16+grp*4+0] + s_red[16+grp*4+1] + s_red[16+grp*4+2] + s_red[16+grp*4+3];
            __syncthreads();
            float mux = sx * (1.0f / FD), mun = sn * (1.0f / FD);

            float4 xc = {xv.x-mux, xv.y-mux, xv.z-mux, xv.w-mux};
            float4 nc = {nv.x-mun, nv.y-mun, nv.z-mun, nv.w-mun};
            float vx = xc.x*xc.x + xc.y*xc.y + xc.z*xc.z + xc.w*xc.w;
            float vn = nc.x*nc.x + nc.y*nc.y + nc.z*nc.z + nc.w*nc.w;
            #pragma unroll
            for (int o = 16; o; o >>= 1) {
                vx += __shfl_down_sync(0xffffffffu, vx, o);
                vn += __shfl_down_sync(0xffffffffu, vn, o);
            }
            if (glane == 0) { s_red[grp * 4 + gwp] = vx; s_red[16 + grp * 4 + gwp] = vn; }
            __syncthreads();
            vx = s_red[grp*4+0] + s_red[grp*4+1] + s_red[grp*4+2] + s_red[grp*4+3];
            vn = s_red[16+grp*4+0] + s_red[16+grp*4+1] + s_red[16+grp*4+2] + s_red[16+grp*4+3];
            __syncthreads();

            float sxi = 1.0f / sqrtf(vx * (1.0f / FD) + 1e-5f);
            float sni = 1.4142135623730951f / sqrtf(vn * (1.0f / FD) + 1e-5f);

            float4 xl = {xc.x*sxi, xc.y*sxi, xc.z*sxi, xc.w*sxi};
            ((float4*)(g_xln + (size_t)row * FD))[gt] = xl;

            int tv = tn[row];
            float somab = g_somab[tv];
            float4 o;
            o.x = somab * sgnf(xl.x) * fabsf(nc.x * sni);
            o.y = somab * sgnf(xl.y) * fabsf(nc.y * sni);
            o.z = somab * sgnf(xl.z) * fabsf(nc.z * sni);
            o.w = somab * sgnf(xl.w) * fabsf(nc.w * sni);
            if (tv == 0) {
                float sab = g_sab[0];
                o.x += sab*xl.x; o.y += sab*xl.y; o.z += sab*xl.z; o.w += sab*xl.w;
            }
            ((float4*)(out + (size_t)row * FD))[gt] = o;

            const float4 te = ((const float4*)(table + (size_t)tv * HH))[gt];
            ((float4*)(out + (size_t)NN * FD + (size_t)row * HH))[gt] = te;
        }
    }
    gbar();

    // ===== Phase D: per-target pull chain  w = (negL^T)^p e_r ===============
    for (int ti = bid; ti < ntgt; ti += GB) {
        int r = g_trow[ti], t = g_tt[ti];
        int p = (t * (t + 1)) >> 1;                 // 1, 3, or 6
        float* w  = s_f;
        float* wn = s_f + NN;
        for (int i = tid; i < NN; i += BT) w[i] = 0.0f;
        __syncthreads();
        if (tid == 0) w[r] = 1.0f;
        __syncthreads();
        for (int a = 0; a < p; a++) {
            for (int i = tid; i < NN; i += BT) {
                int beg = g_rowptr[i], end = g_rowptr[i + 1];
                float acc = 0.0f;
                for (int e = beg; e < end; e++) acc += w[(int)g_cols[e]];
                wn[i] = acc * (1.0f / NN) - g_rowsum[i] * w[i];
            }
            __syncthreads();
            float* t_ = w; w = wn; wn = t_;
        }
        for (int i = tid; i < NN; i += BT) g_wvec[(size_t)ti * NN + i] = w[i];
        __syncthreads();
    }
    gbar();

    // ===== Phase E: contraction out[r,:] += sab[t] * (w^T X)  + cleanup =====
    for (int i = g; i < NN * W32; i += GB * BT) { g_fwd[i] = 0u; g_rev[i] = 0u; }
    if (g == 0) g_tcount = 0;

    int ntask = ntgt * 4;                          // 4 chunks of 128 cols
    for (int task = bid; task < ntask; task += GB) {
        int ti = task >> 2, chunk = task & 3, col0 = chunk * 128;
        int r = g_trow[ti];
        float coef = g_sab[g_tt[ti]];
        for (int i = tid; i < NN; i += BT) s_f[i] = g_wvec[(size_t)ti * NN + i];
        __syncthreads();
        int jsl = tid >> 7, c = tid & 127;
        float acc = 0.0f;
        int j0 = jsl * 256;
        #pragma unroll 4
        for (int j = j0; j < j0 + 256; j++)
            acc += s_f[j] * g_xln[(size_t)j * FD + col0 + c];
        s_f[NN + jsl * 128 + c] = acc;
        __syncthreads();
        if (jsl == 0) {
            float tot = s_f[NN + c] + s_f[NN + 128 + c]
                      + s_f[NN + 256 + c] + s_f[NN + 384 + c];
            out[(size_t)r * FD + col0 + c] += coef * tot;
        }
        __syncthreads();
    }
}

// ---------------- orchestration: ONE launch ---------------------------------
extern "C" void kernel_launch(void* const* d_in, const int* in_sizes, int n_in,
                              void* d_out, int out_size) {
    const float* x     = (const float*)d_in[0];
    const float* noise = (const float*)d_in[1];
    const float* table = (const float*)d_in[2];
    const int*   src   = (const int*)d_in[3];
    const int*   dst   = (const int*)d_in[4];
    const int*   tn    = (const int*)d_in[5];
    int E = in_sizes[3];
    float* out = (float*)d_out;

    k_all<<<GB, BT>>>(x, noise, table, src, dst, tn, out, E);
}

// round 10
// speedup vs baseline: 4.5349x; 1.0222x over previous
#include <cuda_runtime.h>
#include <math.h>

#define NN 1024
#define FD 512
#define TT 128
#define HH 512
#define W32 (NN/32)
#define GB  128            // persistent grid: 128 blocks <= 148 SMs (co-resident)
#define BT  512            // threads per block
#define MAXTGT NN

// ---------------- device globals (zero-init; restored clean at kernel end) --
__device__ unsigned       g_fwd[NN * W32];     // forward adjacency bitmap
__device__ unsigned       g_rev[NN * W32];     // reverse adjacency bitmap
__device__ int            g_rowptr[NN + 1];    // rev CSR rowptr (rebuilt each call)
__device__ unsigned short g_cols[32768];       // rev CSR cols
__device__ float          g_rowsum[NN];        // fwd distinct-degree / n
__device__ float          g_xln[NN * FD];      // LN(x)
__device__ float          g_sab[TT];
__device__ float          g_somab[TT];
__device__ int            g_trow[MAXTGT];
__device__ int            g_tt[MAXTGT];
__device__ int            g_tcount;            // cleared at end
__device__ float          g_wvec[(size_t)MAXTGT * NN];   // per-target propagated vectors
__device__ unsigned       g_bar_cnt;           // grid barrier state
__device__ unsigned       g_bar_gen;

// ---------------- grid barrier (all GB blocks resident by construction) -----
__device__ __forceinline__ void gbar() {
    __threadfence();
    __syncthreads();
    if (threadIdx.x == 0) {
        unsigned gen = *(volatile unsigned*)&g_bar_gen;
        if (atomicAdd(&g_bar_cnt, 1u) == GB - 1) {
            g_bar_cnt = 0;
            __threadfence();
            atomicExch(&g_bar_gen, gen + 1u);
        } else {
            while (*(volatile unsigned*)&g_bar_gen == gen) { }
        }
    }
    __syncthreads();
    __threadfence();
}

__device__ __forceinline__ float sgnf(float v) {
    return (v > 0.0f) ? 1.0f : ((v < 0.0f) ? -1.0f : 0.0f);
}

// ---------------- the whole problem in one persistent kernel ----------------
__global__ void __launch_bounds__(BT) k_all(
    const float* __restrict__ x, const float* __restrict__ noise,
    const float* __restrict__ table, const int* __restrict__ src,
    const int* __restrict__ dst, const int* __restrict__ tn,
    float* __restrict__ out, int E)
{
    __shared__ float  s_f[2048];      // chain ping-pong / contract w + staging
    __shared__ int    s_scan[2048];   // scan double-buffer
    __shared__ float  s_red[32];      // LN reductions
    __shared__ float  s_wsum[4];      // schedule prefix

    const int bid = blockIdx.x, tid = threadIdx.x;
    const int g   = bid * BT + tid;

    // ===== Phase A: edges into bitmaps (pre-cleaned) + beta schedule ========
    for (int e = g; e < E; e += GB * BT) {
        int s = src[e], d = dst[e];
        atomicOr(&g_fwd[s * W32 + (d >> 5)], 1u << (d & 31));
        atomicOr(&g_rev[d * W32 + (s >> 5)], 1u << (s & 31));
    }
    if (bid == 0) {
        // parallel FP32 schedule: ab_t = exp(prefix of log1p(-beta)).
        // fp32 transcendentals (MUFU-backed) — the fp64 versions are software
        // DFMA chains on B300's budget DP pipe and dominated the runtime.
        int lane = tid & 31, w = tid >> 5;
        float p = 0.0f;
        if (tid < TT) {
            float s = -6.0f + 12.0f * (float)tid * (1.0f / (float)(TT - 1));
            float beta = 1.0f / (1.0f + expf(-s)) * (0.02f - 1e-4f) + 1e-4f;
            p = log1pf(-beta);
            #pragma unroll
            for (int o = 1; o < 32; o <<= 1) {
                float v = __shfl_up_sync(0xffffffffu, p, o);
                if (lane >= o) p += v;
            }
            if (lane == 31) s_wsum[w] = p;
        }
        __syncthreads();
        if (tid < TT) {
            float base = 0.0f;
            #pragma unroll
            for (int ww = 0; ww < 4; ww++) if (ww < w) base += s_wsum[ww];
            float ab = expf(base + p);
            g_sab[tid]   = sqrtf(ab);
            g_somab[tid] = sqrtf(1.0f - ab);
        }
    }
    gbar();

    // ===== Phase B: rev rowptr scan (block 0) | rowsum + target list ========
    if (bid == 0) {
        int* a = s_scan; int* b = s_scan + NN;
        for (int i = tid; i < NN; i += BT) {
            int d = 0;
            #pragma unroll
            for (int ww = 0; ww < W32; ww++) d += __popc(g_rev[i * W32 + ww]);
            a[i] = d;
        }
        __syncthreads();
        for (int off = 1; off < NN; off <<= 1) {
            for (int i = tid; i < NN; i += BT)
                b[i] = a[i] + ((i >= off) ? a[i - off] : 0);
            __syncthreads();
            int* t_ = a; a = b; b = t_;
        }
        for (int i = tid; i < NN; i += BT) g_rowptr[i + 1] = a[i];
        if (tid == 0) g_rowptr[0] = 0;
    } else {
        int i = (bid - 1) * BT + tid;
        if (i < NN) {
            int d = 0;
            #pragma unroll
            for (int ww = 0; ww < W32; ww++) d += __popc(g_fwd[i * W32 + ww]);
            g_rowsum[i] = (float)d * (1.0f / NN);
            int t = tn[i];
            if (t >= 1 && t <= 3) {
                int slot = atomicAdd(&g_tcount, 1);
                g_trow[slot] = i; g_tt[slot] = t;
            }
        }
    }
    gbar();
    const int ntgt = g_tcount;     // stable from here until end-of-kernel reset

    // ===== Phase C: fill rev CSR (warp/row) + LN/noise/base-out/time-emb ====
    {
        int gw = bid * (BT / 32) + (tid >> 5);
        int lane = tid & 31;
        if (gw < NN) {
            unsigned b = g_rev[gw * W32 + lane];
            int cnt = __popc(b);
            int pre = cnt;
            #pragma unroll
            for (int o = 1; o < 32; o <<= 1) {
                int v = __shfl_up_sync(0xffffffffu, pre, o);
                if (lane >= o) pre += v;
            }
            pre -= cnt;
            int base = g_rowptr[gw] + pre;
            while (b) {
                int bit = __ffs(b) - 1;
                g_cols[base++] = (unsigned short)(lane * 32 + bit);
                b &= b - 1;
            }
        }
    }
    __syncthreads();
    {
        // 4 groups of 128 threads; 2 iterations -> 8 rows per block
        int grp = tid >> 7, gt = tid & 127;
        int glane = gt & 31, gwp = gt >> 5;
        #pragma unroll
        for (int it = 0; it < 2; it++) {
            int row = bid * 8 + it * 4 + grp;
            const float4 xv = ((const float4*)(x + (size_t)row * FD))[gt];
            const float4 nv = ((const float4*)(noise + (size_t)row * FD))[gt];

            float sx = xv.x + xv.y + xv.z + xv.w;
            float sn = nv.x + nv.y + nv.z + nv.w;
            #pragma unroll
            for (int o = 16; o; o >>= 1) {
                sx += __shfl_down_sync(0xffffffffu, sx, o);
                sn += __shfl_down_sync(0xffffffffu, sn, o);
            }
            if (glane == 0) { s_red[grp * 4 + gwp] = sx; s_red[16 + grp * 4 + gwp] = sn; }
            __syncthreads();
            sx = s_red[grp*4+0] + s_red[grp*4+1] + s_red[grp*4+2] + s_red[grp*4+3];
            sn = s_red[16+grp*4+0] + s_red[16+grp*4+1] + s_red[16+grp*4+2] + s_red[16+grp*4+3];
            __syncthreads();
            float mux = sx * (1.0f / FD), mun = sn * (1.0f / FD);

            float4 xc = {xv.x-mux, xv.y-mux, xv.z-mux, xv.w-mux};
            float4 nc = {nv.x-mun, nv.y-mun, nv.z-mun, nv.w-mun};
            float vx = xc.x*xc.x + xc.y*xc.y + xc.z*xc.z + xc.w*xc.w;
            float vn = nc.x*nc.x + nc.y*nc.y + nc.z*nc.z + nc.w*nc.w;
            #pragma unroll
            for (int o = 16; o; o >>= 1) {
                vx += __shfl_down_sync(0xffffffffu, vx, o);
                vn += __shfl_down_sync(0xffffffffu, vn, o);
            }
            if (glane == 0) { s_red[grp * 4 + gwp] = vx; s_red[16 + grp * 4 + gwp] = vn; }
            __syncthreads();
            vx = s_red[grp*4+0] + s_red[grp*4+1] + s_red[grp*4+2] + s_red[grp*4+3];
            vn = s_red[16+grp*4+0] + s_red[16+grp*4+1] + s_red[16+grp*4+2] + s_red[16+grp*4+3];
            __syncthreads();

            float sxi = 1.0f / sqrtf(vx * (1.0f / FD) + 1e-5f);
            float sni = 1.4142135623730951f / sqrtf(vn * (1.0f / FD) + 1e-5f);

            float4 xl = {xc.x*sxi, xc.y*sxi, xc.z*sxi, xc.w*sxi};
            ((float4*)(g_xln + (size_t)row * FD))[gt] = xl;

            int tv = tn[row];
            float somab = g_somab[tv];
            float4 o;
            o.x = somab * sgnf(xl.x) * fabsf(nc.x * sni);
            o.y = somab * sgnf(xl.y) * fabsf(nc.y * sni);
            o.z = somab * sgnf(xl.z) * fabsf(nc.z * sni);
            o.w = somab * sgnf(xl.w) * fabsf(nc.w * sni);
            if (tv == 0) {
                float sab = g_sab[0];
                o.x += sab*xl.x; o.y += sab*xl.y; o.z += sab*xl.z; o.w += sab*xl.w;
            }
            ((float4*)(out + (size_t)row * FD))[gt] = o;

            const float4 te = ((const float4*)(table + (size_t)tv * HH))[gt];
            ((float4*)(out + (size_t)NN * FD + (size_t)row * HH))[gt] = te;
        }
    }
    gbar();

    // ===== Phase D: per-target pull chain  w = (negL^T)^p e_r ===============
    for (int ti = bid; ti < ntgt; ti += GB) {
        int r = g_trow[ti], t = g_tt[ti];
        int p = (t * (t + 1)) >> 1;                 // 1, 3, or 6
        float* w  = s_f;
        float* wn = s_f + NN;
        for (int i = tid; i < NN; i += BT) w[i] = 0.0f;
        __syncthreads();
        if (tid == 0) w[r] = 1.0f;
        __syncthreads();
        for (int a = 0; a < p; a++) {
            for (int i = tid; i < NN; i += BT) {
                int beg = g_rowptr[i], end = g_rowptr[i + 1];
                float acc = 0.0f;
                for (int e = beg; e < end; e++) acc += w[(int)g_cols[e]];
                wn[i] = acc * (1.0f / NN) - g_rowsum[i] * w[i];
            }
            __syncthreads();
            float* t_ = w; w = wn; wn = t_;
        }
        for (int i = tid; i < NN; i += BT) g_wvec[(size_t)ti * NN + i] = w[i];
        __syncthreads();
    }
    gbar();

    // ===== Phase E: contraction out[r,:] += sab[t] * (w^T X)  + cleanup =====
    for (int i = g; i < NN * W32; i += GB * BT) { g_fwd[i] = 0u; g_rev[i] = 0u; }
    if (g == 0) g_tcount = 0;

    int ntask = ntgt * 4;                          // 4 chunks of 128 cols
    for (int task = bid; task < ntask; task += GB) {
        int ti = task >> 2, chunk = task & 3, col0 = chunk * 128;
        int r = g_trow[ti];
        float coef = g_sab[g_tt[ti]];
        for (int i = tid; i < NN; i += BT) s_f[i] = g_wvec[(size_t)ti * NN + i];
        __syncthreads();
        int jsl = tid >> 7, c = tid & 127;
        float acc = 0.0f;
        int j0 = jsl * 256;
        #pragma unroll 4
        for (int j = j0; j < j0 + 256; j++)
            acc += s_f[j] * g_xln[(size_t)j * FD + col0 + c];
        s_f[NN + jsl * 128 + c] = acc;
        __syncthreads();
        if (jsl == 0) {
            float tot = s_f[NN + c] + s_f[NN + 128 + c]
                      + s_f[NN + 256 + c] + s_f[NN + 384 + c];
            out[(size_t)r * FD + col0 + c] += coef * tot;
        }
        __syncthreads();
    }
}

// ---------------- orchestration: ONE launch ---------------------------------
extern "C" void kernel_launch(void* const* d_in, const int* in_sizes, int n_in,
                              void* d_out, int out_size) {
    const float* x     = (const float*)d_in[0];
    const float* noise = (const float*)d_in[1];
    const float* table = (const float*)d_in[2];
    const int*   src   = (const int*)d_in[3];
    const int*   dst   = (const int*)d_in[4];
    const int*   tn    = (const int*)d_in[5];
    int E = in_sizes[3];
    float* out = (float*)d_out;

    k_all<<<GB, BT>>>(x, noise, table, src, dst, tn, out, E);
}